// round 1
// baseline (speedup 1.0000x reference)
#include <cuda_runtime.h>
#include <cstdint>

#define IN_CH  512
#define HID    16
#define OUT_CH 64
#define MAX_NODES 100352
#define MAX_EDGES 3276800

// ---- scratch (device globals; no allocation allowed) ----
__device__ float g_deg [MAX_NODES];
__device__ float g_dinv[MAX_NODES];
__device__ float g_h1  [MAX_NODES * HID];
__device__ float g_agg1[MAX_NODES * HID];
__device__ float g_agg2[MAX_NODES * HID];
__device__ float g_norm[MAX_EDGES];

// vectorized f32 reduction (sm_90+): 1 request instead of 4 scalar atomics
__device__ __forceinline__ void red_add_v4(float* p, float4 v) {
    asm volatile("red.global.add.v4.f32 [%0], {%1,%2,%3,%4};"
                 :: "l"(p), "f"(v.x), "f"(v.y), "f"(v.z), "f"(v.w) : "memory");
}

// ---------------------------------------------------------------- zero
__global__ void zero_kernel(int n) {
    int i = blockIdx.x * blockDim.x + threadIdx.x;
    int t = n * HID;
    if (i < t) { g_agg1[i] = 0.f; g_agg2[i] = 0.f; }
    if (i < n) g_deg[i] = 0.f;
}

// ---------------------------------------------------------------- degree
__global__ void deg_kernel(const int* __restrict__ ei1, const float* __restrict__ w1, int E1,
                           const int* __restrict__ ei2, const float* __restrict__ w2, int E2) {
    int i = blockIdx.x * blockDim.x + threadIdx.x;
    if (i < E1) {
        atomicAdd(&g_deg[ei1[i]], w1[i]);
    } else {
        int j = i - E1;
        if (j < E2) atomicAdd(&g_deg[ei2[j]], w2[j]);
    }
}

__global__ void dinv_kernel(int n) {
    int i = blockIdx.x * blockDim.x + threadIdx.x;
    if (i >= n) return;
    float d = g_deg[i];
    g_dinv[i] = d > 0.f ? rsqrtf(fmaxf(d, 1e-12f)) : 0.f;
}

// ---------------------------------------------------------------- h1 = x @ W1
// lane-per-node: warp handles 32 nodes. x staged through per-warp shared tile
// (stride-65 padding -> conflict-free (lane+k)%32 banks). W1 broadcast from shared.
#define G1_WARPS   8
#define G1_THREADS (G1_WARPS * 32)
#define G1_KCHUNK  64
#define G1_XS_STRIDE 65
#define G1_SMEM_FLOATS (IN_CH * HID + G1_WARPS * 32 * G1_XS_STRIDE)

__global__ void gemm1_kernel(const float* __restrict__ x, const float* __restrict__ W1, int n) {
    extern __shared__ float smem[];
    float* Ws = smem;  // [512][16] row-major
    const int warp = threadIdx.x >> 5;
    const int lane = threadIdx.x & 31;
    float* xs = smem + IN_CH * HID + warp * (32 * G1_XS_STRIDE);

    for (int t = threadIdx.x; t < IN_CH * HID / 4; t += blockDim.x)
        ((float4*)Ws)[t] = ((const float4*)W1)[t];
    __syncthreads();

    const int nodebase = blockIdx.x * G1_THREADS + warp * 32;
    const int node = nodebase + lane;

    float acc[HID];
#pragma unroll
    for (int j = 0; j < HID; j++) acc[j] = 0.f;

    for (int kc = 0; kc < IN_CH; kc += G1_KCHUNK) {
        // stage 32 rows x 64 floats (coalesced float4 loads)
#pragma unroll
        for (int t = 0; t < 16; t++) {
            int idx = t * 32 + lane;      // 0..511
            int r   = idx >> 4;           // row in tile
            int c   = idx & 15;           // float4 column
            int nd  = nodebase + r;
            float4 v = make_float4(0.f, 0.f, 0.f, 0.f);
            if (nd < n) v = ((const float4*)x)[(size_t)nd * (IN_CH / 4) + (kc >> 2) + c];
            float* p = xs + r * G1_XS_STRIDE + c * 4;
            p[0] = v.x; p[1] = v.y; p[2] = v.z; p[3] = v.w;
        }
        __syncwarp();
        const float* xrow = xs + lane * G1_XS_STRIDE;
#pragma unroll 8
        for (int k = 0; k < G1_KCHUNK; k++) {
            float xv = xrow[k];
            const float4* wr = (const float4*)(Ws + (kc + k) * HID);
            float4 wa = wr[0], wb = wr[1], wc = wr[2], wd = wr[3];
            acc[0]  += xv * wa.x; acc[1]  += xv * wa.y; acc[2]  += xv * wa.z; acc[3]  += xv * wa.w;
            acc[4]  += xv * wb.x; acc[5]  += xv * wb.y; acc[6]  += xv * wb.z; acc[7]  += xv * wb.w;
            acc[8]  += xv * wc.x; acc[9]  += xv * wc.y; acc[10] += xv * wc.z; acc[11] += xv * wc.w;
            acc[12] += xv * wd.x; acc[13] += xv * wd.y; acc[14] += xv * wd.z; acc[15] += xv * wd.w;
        }
        __syncwarp();
    }

    if (node < n) {
        float4* o = (float4*)(g_h1 + (size_t)node * HID);
        o[0] = make_float4(acc[0],  acc[1],  acc[2],  acc[3]);
        o[1] = make_float4(acc[4],  acc[5],  acc[6],  acc[7]);
        o[2] = make_float4(acc[8],  acc[9],  acc[10], acc[11]);
        o[3] = make_float4(acc[12], acc[13], acc[14], acc[15]);
    }
}

// ---------------------------------------------------------------- scatter
// LAYER==1: src=g_h1, dst=g_agg1, compute+store norm, no relu
// LAYER==2: src=g_agg1, dst=g_agg2, read norm, relu(v + b1)
template <int LAYER>
__global__ void scatter_kernel(const int* __restrict__ ei1, const float* __restrict__ wt1, int E1,
                               const int* __restrict__ ei2, const float* __restrict__ wt2, int E2,
                               const float* __restrict__ b1) {
    int i = blockIdx.x * blockDim.x + threadIdx.x;
    int row, col;
    float nrm;
    if (i < E1) {
        row = ei1[i]; col = ei1[E1 + i];
        if (LAYER == 1) { nrm = g_dinv[row] * wt1[i] * g_dinv[col]; g_norm[i] = nrm; }
        else            { nrm = g_norm[i]; }
    } else {
        int j = i - E1;
        if (j >= E2) return;
        row = ei2[j]; col = ei2[E2 + j];
        if (LAYER == 1) { nrm = g_dinv[row] * wt2[j] * g_dinv[col]; g_norm[i] = nrm; }
        else            { nrm = g_norm[i]; }
    }

    const float* src = (LAYER == 1) ? g_h1 : g_agg1;
    float*       dst = (LAYER == 1) ? g_agg1 : g_agg2;

    const float4* s = (const float4*)(src + (size_t)col * HID);
    float4 v0 = s[0], v1 = s[1], v2 = s[2], v3 = s[3];
    if (LAYER == 2) {
        const float4* b = (const float4*)b1;
        float4 b0 = b[0], bb = b[1], bc = b[2], bd = b[3];
        v0.x = fmaxf(v0.x + b0.x, 0.f); v0.y = fmaxf(v0.y + b0.y, 0.f);
        v0.z = fmaxf(v0.z + b0.z, 0.f); v0.w = fmaxf(v0.w + b0.w, 0.f);
        v1.x = fmaxf(v1.x + bb.x, 0.f); v1.y = fmaxf(v1.y + bb.y, 0.f);
        v1.z = fmaxf(v1.z + bb.z, 0.f); v1.w = fmaxf(v1.w + bb.w, 0.f);
        v2.x = fmaxf(v2.x + bc.x, 0.f); v2.y = fmaxf(v2.y + bc.y, 0.f);
        v2.z = fmaxf(v2.z + bc.z, 0.f); v2.w = fmaxf(v2.w + bc.w, 0.f);
        v3.x = fmaxf(v3.x + bd.x, 0.f); v3.y = fmaxf(v3.y + bd.y, 0.f);
        v3.z = fmaxf(v3.z + bd.z, 0.f); v3.w = fmaxf(v3.w + bd.w, 0.f);
    }
    v0.x *= nrm; v0.y *= nrm; v0.z *= nrm; v0.w *= nrm;
    v1.x *= nrm; v1.y *= nrm; v1.z *= nrm; v1.w *= nrm;
    v2.x *= nrm; v2.y *= nrm; v2.z *= nrm; v2.w *= nrm;
    v3.x *= nrm; v3.y *= nrm; v3.z *= nrm; v3.w *= nrm;

    float* d = dst + (size_t)row * HID;
    red_add_v4(d + 0,  v0);
    red_add_v4(d + 4,  v1);
    red_add_v4(d + 8,  v2);
    red_add_v4(d + 12, v3);
}

// ---------------------------------------------------------------- out = log_softmax(agg2 @ W2 + b2)
#define OUT_WARPS 8
__global__ void out_kernel(const float* __restrict__ W2, const float* __restrict__ b2,
                           float* __restrict__ out, int n) {
    __shared__ float W2s[HID * OUT_CH];
    for (int t = threadIdx.x; t < HID * OUT_CH / 4; t += blockDim.x)
        ((float4*)W2s)[t] = ((const float4*)W2)[t];
    __syncthreads();

    int warp = threadIdx.x >> 5, lane = threadIdx.x & 31;
    int node = blockIdx.x * OUT_WARPS + warp;
    if (node >= n) return;

    const float4* a4 = (const float4*)(g_agg2 + (size_t)node * HID);
    float4 a0 = a4[0], a1 = a4[1], a2 = a4[2], a3 = a4[3];
    float a[16];
    a[0]  = a0.x; a[1]  = a0.y; a[2]  = a0.z; a[3]  = a0.w;
    a[4]  = a1.x; a[5]  = a1.y; a[6]  = a1.z; a[7]  = a1.w;
    a[8]  = a2.x; a[9]  = a2.y; a[10] = a2.z; a[11] = a2.w;
    a[12] = a3.x; a[13] = a3.y; a[14] = a3.z; a[15] = a3.w;

    float acc0 = b2[lane];
    float acc1 = b2[lane + 32];
#pragma unroll
    for (int k = 0; k < HID; k++) {
        acc0 += a[k] * W2s[k * OUT_CH + lane];
        acc1 += a[k] * W2s[k * OUT_CH + lane + 32];
    }

    float m = fmaxf(acc0, acc1);
#pragma unroll
    for (int off = 16; off >= 1; off >>= 1)
        m = fmaxf(m, __shfl_xor_sync(0xffffffffu, m, off));
    float s = expf(acc0 - m) + expf(acc1 - m);
#pragma unroll
    for (int off = 16; off >= 1; off >>= 1)
        s += __shfl_xor_sync(0xffffffffu, s, off);
    float lse = m + logf(s);

    out[(size_t)node * OUT_CH + lane]      = acc0 - lse;
    out[(size_t)node * OUT_CH + lane + 32] = acc1 - lse;
}

// ---------------------------------------------------------------- launch
extern "C" void kernel_launch(void* const* d_in, const int* in_sizes, int n_in,
                              void* d_out, int out_size) {
    const float* x   = (const float*)d_in[0];
    const int*   ei1 = (const int*)  d_in[1];
    const float* ew1 = (const float*)d_in[2];
    const int*   ei2 = (const int*)  d_in[3];
    const float* ew2 = (const float*)d_in[4];
    const float* W1  = (const float*)d_in[5];
    const float* b1  = (const float*)d_in[6];
    const float* W2  = (const float*)d_in[7];
    const float* b2  = (const float*)d_in[8];
    float* out = (float*)d_out;

    int n  = in_sizes[0] / IN_CH;
    int E1 = in_sizes[2];
    int E2 = in_sizes[4];
    int Et = E1 + E2;

    const int G1_SMEM = G1_SMEM_FLOATS * (int)sizeof(float);
    cudaFuncSetAttribute(gemm1_kernel, cudaFuncAttributeMaxDynamicSharedMemorySize, G1_SMEM);

    zero_kernel<<<(n * HID + 255) / 256, 256>>>(n);
    deg_kernel<<<(Et + 255) / 256, 256>>>(ei1, ew1, E1, ei2, ew2, E2);
    dinv_kernel<<<(n + 255) / 256, 256>>>(n);
    gemm1_kernel<<<(n + G1_THREADS - 1) / G1_THREADS, G1_THREADS, G1_SMEM>>>(x, W1, n);
    scatter_kernel<1><<<(Et + 255) / 256, 256>>>(ei1, ew1, E1, ei2, ew2, E2, b1);
    scatter_kernel<2><<<(Et + 255) / 256, 256>>>(ei1, ew1, E1, ei2, ew2, E2, b1);
    out_kernel<<<(n + OUT_WARPS - 1) / OUT_WARPS, OUT_WARPS * 32>>>(W2, b2, out, n);
}

// round 2
// speedup vs baseline: 1.0003x; 1.0003x over previous
#include <cuda_runtime.h>
#include <cstdint>

#define IN_CH  512
#define HID    16
#define OUT_CH 64
#define MAX_NODES 100352
#define MAX_EDGES 3276800

// ---- scratch (device globals; no allocation allowed) ----
__device__ float g_deg [MAX_NODES];
__device__ float g_dinv[MAX_NODES];
__device__ float g_h1  [MAX_NODES * HID];
__device__ float g_agg1[MAX_NODES * HID];
__device__ float g_agg2[MAX_NODES * HID];
__device__ float g_norm[MAX_EDGES];

// vectorized f32 reduction (sm_90+): 1 request instead of 4 scalar atomics
__device__ __forceinline__ void red_add_v4(float* p, float4 v) {
    asm volatile("red.global.add.v4.f32 [%0], {%1,%2,%3,%4};"
                 :: "l"(p), "f"(v.x), "f"(v.y), "f"(v.z), "f"(v.w) : "memory");
}

// ---------------------------------------------------------------- zero
__global__ void zero_kernel(int n) {
    int i = blockIdx.x * blockDim.x + threadIdx.x;
    int t = n * HID;
    if (i < t) { g_agg1[i] = 0.f; g_agg2[i] = 0.f; }
    if (i < n) g_deg[i] = 0.f;
}

// ---------------------------------------------------------------- degree
__global__ void deg_kernel(const int* __restrict__ ei1, const float* __restrict__ w1, int E1,
                           const int* __restrict__ ei2, const float* __restrict__ w2, int E2) {
    int i = blockIdx.x * blockDim.x + threadIdx.x;
    if (i < E1) {
        atomicAdd(&g_deg[ei1[i]], w1[i]);
    } else {
        int j = i - E1;
        if (j < E2) atomicAdd(&g_deg[ei2[j]], w2[j]);
    }
}

__global__ void dinv_kernel(int n) {
    int i = blockIdx.x * blockDim.x + threadIdx.x;
    if (i >= n) return;
    float d = g_deg[i];
    g_dinv[i] = d > 0.f ? rsqrtf(fmaxf(d, 1e-12f)) : 0.f;
}

// ---------------------------------------------------------------- h1 = x @ W1
// lane-per-node: warp handles 32 nodes. x staged through per-warp shared tile
// (stride-65 padding -> conflict-free (lane+k)%32 banks). W1 broadcast from shared.
#define G1_WARPS   8
#define G1_THREADS (G1_WARPS * 32)
#define G1_KCHUNK  64
#define G1_XS_STRIDE 65
#define G1_SMEM_FLOATS (IN_CH * HID + G1_WARPS * 32 * G1_XS_STRIDE)

__global__ void gemm1_kernel(const float* __restrict__ x, const float* __restrict__ W1, int n) {
    extern __shared__ float smem[];
    float* Ws = smem;  // [512][16] row-major
    const int warp = threadIdx.x >> 5;
    const int lane = threadIdx.x & 31;
    float* xs = smem + IN_CH * HID + warp * (32 * G1_XS_STRIDE);

    for (int t = threadIdx.x; t < IN_CH * HID / 4; t += blockDim.x)
        ((float4*)Ws)[t] = ((const float4*)W1)[t];
    __syncthreads();

    const int nodebase = blockIdx.x * G1_THREADS + warp * 32;
    const int node = nodebase + lane;

    float acc[HID];
#pragma unroll
    for (int j = 0; j < HID; j++) acc[j] = 0.f;

    for (int kc = 0; kc < IN_CH; kc += G1_KCHUNK) {
        // stage 32 rows x 64 floats (coalesced float4 loads)
#pragma unroll
        for (int t = 0; t < 16; t++) {
            int idx = t * 32 + lane;      // 0..511
            int r   = idx >> 4;           // row in tile
            int c   = idx & 15;           // float4 column
            int nd  = nodebase + r;
            float4 v = make_float4(0.f, 0.f, 0.f, 0.f);
            if (nd < n) v = ((const float4*)x)[(size_t)nd * (IN_CH / 4) + (kc >> 2) + c];
            float* p = xs + r * G1_XS_STRIDE + c * 4;
            p[0] = v.x; p[1] = v.y; p[2] = v.z; p[3] = v.w;
        }
        __syncwarp();
        const float* xrow = xs + lane * G1_XS_STRIDE;
#pragma unroll 8
        for (int k = 0; k < G1_KCHUNK; k++) {
            float xv = xrow[k];
            const float4* wr = (const float4*)(Ws + (kc + k) * HID);
            float4 wa = wr[0], wb = wr[1], wc = wr[2], wd = wr[3];
            acc[0]  += xv * wa.x; acc[1]  += xv * wa.y; acc[2]  += xv * wa.z; acc[3]  += xv * wa.w;
            acc[4]  += xv * wb.x; acc[5]  += xv * wb.y; acc[6]  += xv * wb.z; acc[7]  += xv * wb.w;
            acc[8]  += xv * wc.x; acc[9]  += xv * wc.y; acc[10] += xv * wc.z; acc[11] += xv * wc.w;
            acc[12] += xv * wd.x; acc[13] += xv * wd.y; acc[14] += xv * wd.z; acc[15] += xv * wd.w;
        }
        __syncwarp();
    }

    if (node < n) {
        float4* o = (float4*)(g_h1 + (size_t)node * HID);
        o[0] = make_float4(acc[0],  acc[1],  acc[2],  acc[3]);
        o[1] = make_float4(acc[4],  acc[5],  acc[6],  acc[7]);
        o[2] = make_float4(acc[8],  acc[9],  acc[10], acc[11]);
        o[3] = make_float4(acc[12], acc[13], acc[14], acc[15]);
    }
}

// ---------------------------------------------------------------- scatter
// LAYER==1: src=g_h1, dst=g_agg1, compute+store norm, no relu
// LAYER==2: src=g_agg1, dst=g_agg2, read norm, relu(v + b1)
template <int LAYER>
__global__ void scatter_kernel(const int* __restrict__ ei1, const float* __restrict__ wt1, int E1,
                               const int* __restrict__ ei2, const float* __restrict__ wt2, int E2,
                               const float* __restrict__ b1) {
    int i = blockIdx.x * blockDim.x + threadIdx.x;
    int row, col;
    float nrm;
    if (i < E1) {
        row = ei1[i]; col = ei1[E1 + i];
        if (LAYER == 1) { nrm = g_dinv[row] * wt1[i] * g_dinv[col]; g_norm[i] = nrm; }
        else            { nrm = g_norm[i]; }
    } else {
        int j = i - E1;
        if (j >= E2) return;
        row = ei2[j]; col = ei2[E2 + j];
        if (LAYER == 1) { nrm = g_dinv[row] * wt2[j] * g_dinv[col]; g_norm[i] = nrm; }
        else            { nrm = g_norm[i]; }
    }

    const float* src = (LAYER == 1) ? g_h1 : g_agg1;
    float*       dst = (LAYER == 1) ? g_agg1 : g_agg2;

    const float4* s = (const float4*)(src + (size_t)col * HID);
    float4 v0 = s[0], v1 = s[1], v2 = s[2], v3 = s[3];
    if (LAYER == 2) {
        const float4* b = (const float4*)b1;
        float4 b0 = b[0], bb = b[1], bc = b[2], bd = b[3];
        v0.x = fmaxf(v0.x + b0.x, 0.f); v0.y = fmaxf(v0.y + b0.y, 0.f);
        v0.z = fmaxf(v0.z + b0.z, 0.f); v0.w = fmaxf(v0.w + b0.w, 0.f);
        v1.x = fmaxf(v1.x + bb.x, 0.f); v1.y = fmaxf(v1.y + bb.y, 0.f);
        v1.z = fmaxf(v1.z + bb.z, 0.f); v1.w = fmaxf(v1.w + bb.w, 0.f);
        v2.x = fmaxf(v2.x + bc.x, 0.f); v2.y = fmaxf(v2.y + bc.y, 0.f);
        v2.z = fmaxf(v2.z + bc.z, 0.f); v2.w = fmaxf(v2.w + bc.w, 0.f);
        v3.x = fmaxf(v3.x + bd.x, 0.f); v3.y = fmaxf(v3.y + bd.y, 0.f);
        v3.z = fmaxf(v3.z + bd.z, 0.f); v3.w = fmaxf(v3.w + bd.w, 0.f);
    }
    v0.x *= nrm; v0.y *= nrm; v0.z *= nrm; v0.w *= nrm;
    v1.x *= nrm; v1.y *= nrm; v1.z *= nrm; v1.w *= nrm;
    v2.x *= nrm; v2.y *= nrm; v2.z *= nrm; v2.w *= nrm;
    v3.x *= nrm; v3.y *= nrm; v3.z *= nrm; v3.w *= nrm;

    float* d = dst + (size_t)row * HID;
    red_add_v4(d + 0,  v0);
    red_add_v4(d + 4,  v1);
    red_add_v4(d + 8,  v2);
    red_add_v4(d + 12, v3);
}

// ---------------------------------------------------------------- out = log_softmax(agg2 @ W2 + b2)
#define OUT_WARPS 8
__global__ void out_kernel(const float* __restrict__ W2, const float* __restrict__ b2,
                           float* __restrict__ out, int n) {
    __shared__ float W2s[HID * OUT_CH];
    for (int t = threadIdx.x; t < HID * OUT_CH / 4; t += blockDim.x)
        ((float4*)W2s)[t] = ((const float4*)W2)[t];
    __syncthreads();

    int warp = threadIdx.x >> 5, lane = threadIdx.x & 31;
    int node = blockIdx.x * OUT_WARPS + warp;
    if (node >= n) return;

    const float4* a4 = (const float4*)(g_agg2 + (size_t)node * HID);
    float4 a0 = a4[0], a1 = a4[1], a2 = a4[2], a3 = a4[3];
    float a[16];
    a[0]  = a0.x; a[1]  = a0.y; a[2]  = a0.z; a[3]  = a0.w;
    a[4]  = a1.x; a[5]  = a1.y; a[6]  = a1.z; a[7]  = a1.w;
    a[8]  = a2.x; a[9]  = a2.y; a[10] = a2.z; a[11] = a2.w;
    a[12] = a3.x; a[13] = a3.y; a[14] = a3.z; a[15] = a3.w;

    float acc0 = b2[lane];
    float acc1 = b2[lane + 32];
#pragma unroll
    for (int k = 0; k < HID; k++) {
        acc0 += a[k] * W2s[k * OUT_CH + lane];
        acc1 += a[k] * W2s[k * OUT_CH + lane + 32];
    }

    float m = fmaxf(acc0, acc1);
#pragma unroll
    for (int off = 16; off >= 1; off >>= 1)
        m = fmaxf(m, __shfl_xor_sync(0xffffffffu, m, off));
    float s = expf(acc0 - m) + expf(acc1 - m);
#pragma unroll
    for (int off = 16; off >= 1; off >>= 1)
        s += __shfl_xor_sync(0xffffffffu, s, off);
    float lse = m + logf(s);

    out[(size_t)node * OUT_CH + lane]      = acc0 - lse;
    out[(size_t)node * OUT_CH + lane + 32] = acc1 - lse;
}

// ---------------------------------------------------------------- launch
extern "C" void kernel_launch(void* const* d_in, const int* in_sizes, int n_in,
                              void* d_out, int out_size) {
    const float* x   = (const float*)d_in[0];
    const int*   ei1 = (const int*)  d_in[1];
    const float* ew1 = (const float*)d_in[2];
    const int*   ei2 = (const int*)  d_in[3];
    const float* ew2 = (const float*)d_in[4];
    const float* W1  = (const float*)d_in[5];
    const float* b1  = (const float*)d_in[6];
    const float* W2  = (const float*)d_in[7];
    const float* b2  = (const float*)d_in[8];
    float* out = (float*)d_out;

    int n  = in_sizes[0] / IN_CH;
    int E1 = in_sizes[2];
    int E2 = in_sizes[4];
    int Et = E1 + E2;

    const int G1_SMEM = G1_SMEM_FLOATS * (int)sizeof(float);
    cudaFuncSetAttribute(gemm1_kernel, cudaFuncAttributeMaxDynamicSharedMemorySize, G1_SMEM);

    zero_kernel<<<(n * HID + 255) / 256, 256>>>(n);
    deg_kernel<<<(Et + 255) / 256, 256>>>(ei1, ew1, E1, ei2, ew2, E2);
    dinv_kernel<<<(n + 255) / 256, 256>>>(n);
    gemm1_kernel<<<(n + G1_THREADS - 1) / G1_THREADS, G1_THREADS, G1_SMEM>>>(x, W1, n);
    scatter_kernel<1><<<(Et + 255) / 256, 256>>>(ei1, ew1, E1, ei2, ew2, E2, b1);
    scatter_kernel<2><<<(Et + 255) / 256, 256>>>(ei1, ew1, E1, ei2, ew2, E2, b1);
    out_kernel<<<(n + OUT_WARPS - 1) / OUT_WARPS, OUT_WARPS * 32>>>(W2, b2, out, n);
}

// round 3
// speedup vs baseline: 1.0005x; 1.0003x over previous
#include <cuda_runtime.h>
#include <cstdint>

#define IN_CH  512
#define HID    16
#define OUT_CH 64
#define MAX_NODES 100352
#define MAX_EDGES 3276800

// ---- scratch (device globals; no allocation allowed) ----
__device__ float g_deg [MAX_NODES];
__device__ float g_dinv[MAX_NODES];
__device__ float g_h1  [MAX_NODES * HID];
__device__ float g_agg1[MAX_NODES * HID];
__device__ float g_agg2[MAX_NODES * HID];
__device__ float g_norm[MAX_EDGES];

// vectorized f32 reduction (sm_90+): 1 request instead of 4 scalar atomics
__device__ __forceinline__ void red_add_v4(float* p, float4 v) {
    asm volatile("red.global.add.v4.f32 [%0], {%1,%2,%3,%4};"
                 :: "l"(p), "f"(v.x), "f"(v.y), "f"(v.z), "f"(v.w) : "memory");
}

// ---------------------------------------------------------------- zero
__global__ void zero_kernel(int n) {
    int i = blockIdx.x * blockDim.x + threadIdx.x;
    int t = n * HID;
    if (i < t) { g_agg1[i] = 0.f; g_agg2[i] = 0.f; }
    if (i < n) g_deg[i] = 0.f;
}

// ---------------------------------------------------------------- degree
__global__ void deg_kernel(const int* __restrict__ ei1, const float* __restrict__ w1, int E1,
                           const int* __restrict__ ei2, const float* __restrict__ w2, int E2) {
    int i = blockIdx.x * blockDim.x + threadIdx.x;
    if (i < E1) {
        atomicAdd(&g_deg[ei1[i]], w1[i]);
    } else {
        int j = i - E1;
        if (j < E2) atomicAdd(&g_deg[ei2[j]], w2[j]);
    }
}

__global__ void dinv_kernel(int n) {
    int i = blockIdx.x * blockDim.x + threadIdx.x;
    if (i >= n) return;
    float d = g_deg[i];
    g_dinv[i] = d > 0.f ? rsqrtf(fmaxf(d, 1e-12f)) : 0.f;
}

// ---------------------------------------------------------------- h1 = x @ W1
// lane-per-node: warp handles 32 nodes. x staged through per-warp shared tile
// (stride-65 padding -> conflict-free (lane+k)%32 banks). W1 broadcast from shared.
#define G1_WARPS   8
#define G1_THREADS (G1_WARPS * 32)
#define G1_KCHUNK  64
#define G1_XS_STRIDE 65
#define G1_SMEM_FLOATS (IN_CH * HID + G1_WARPS * 32 * G1_XS_STRIDE)

__global__ void gemm1_kernel(const float* __restrict__ x, const float* __restrict__ W1, int n) {
    extern __shared__ float smem[];
    float* Ws = smem;  // [512][16] row-major
    const int warp = threadIdx.x >> 5;
    const int lane = threadIdx.x & 31;
    float* xs = smem + IN_CH * HID + warp * (32 * G1_XS_STRIDE);

    for (int t = threadIdx.x; t < IN_CH * HID / 4; t += blockDim.x)
        ((float4*)Ws)[t] = ((const float4*)W1)[t];
    __syncthreads();

    const int nodebase = blockIdx.x * G1_THREADS + warp * 32;
    const int node = nodebase + lane;

    float acc[HID];
#pragma unroll
    for (int j = 0; j < HID; j++) acc[j] = 0.f;

    for (int kc = 0; kc < IN_CH; kc += G1_KCHUNK) {
        // stage 32 rows x 64 floats (coalesced float4 loads)
#pragma unroll
        for (int t = 0; t < 16; t++) {
            int idx = t * 32 + lane;      // 0..511
            int r   = idx >> 4;           // row in tile
            int c   = idx & 15;           // float4 column
            int nd  = nodebase + r;
            float4 v = make_float4(0.f, 0.f, 0.f, 0.f);
            if (nd < n) v = ((const float4*)x)[(size_t)nd * (IN_CH / 4) + (kc >> 2) + c];
            float* p = xs + r * G1_XS_STRIDE + c * 4;
            p[0] = v.x; p[1] = v.y; p[2] = v.z; p[3] = v.w;
        }
        __syncwarp();
        const float* xrow = xs + lane * G1_XS_STRIDE;
#pragma unroll 8
        for (int k = 0; k < G1_KCHUNK; k++) {
            float xv = xrow[k];
            const float4* wr = (const float4*)(Ws + (kc + k) * HID);
            float4 wa = wr[0], wb = wr[1], wc = wr[2], wd = wr[3];
            acc[0]  += xv * wa.x; acc[1]  += xv * wa.y; acc[2]  += xv * wa.z; acc[3]  += xv * wa.w;
            acc[4]  += xv * wb.x; acc[5]  += xv * wb.y; acc[6]  += xv * wb.z; acc[7]  += xv * wb.w;
            acc[8]  += xv * wc.x; acc[9]  += xv * wc.y; acc[10] += xv * wc.z; acc[11] += xv * wc.w;
            acc[12] += xv * wd.x; acc[13] += xv * wd.y; acc[14] += xv * wd.z; acc[15] += xv * wd.w;
        }
        __syncwarp();
    }

    if (node < n) {
        float4* o = (float4*)(g_h1 + (size_t)node * HID);
        o[0] = make_float4(acc[0],  acc[1],  acc[2],  acc[3]);
        o[1] = make_float4(acc[4],  acc[5],  acc[6],  acc[7]);
        o[2] = make_float4(acc[8],  acc[9],  acc[10], acc[11]);
        o[3] = make_float4(acc[12], acc[13], acc[14], acc[15]);
    }
}

// ---------------------------------------------------------------- scatter
// LAYER==1: src=g_h1, dst=g_agg1, compute+store norm, no relu
// LAYER==2: src=g_agg1, dst=g_agg2, read norm, relu(v + b1)
template <int LAYER>
__global__ void scatter_kernel(const int* __restrict__ ei1, const float* __restrict__ wt1, int E1,
                               const int* __restrict__ ei2, const float* __restrict__ wt2, int E2,
                               const float* __restrict__ b1) {
    int i = blockIdx.x * blockDim.x + threadIdx.x;
    int row, col;
    float nrm;
    if (i < E1) {
        row = ei1[i]; col = ei1[E1 + i];
        if (LAYER == 1) { nrm = g_dinv[row] * wt1[i] * g_dinv[col]; g_norm[i] = nrm; }
        else            { nrm = g_norm[i]; }
    } else {
        int j = i - E1;
        if (j >= E2) return;
        row = ei2[j]; col = ei2[E2 + j];
        if (LAYER == 1) { nrm = g_dinv[row] * wt2[j] * g_dinv[col]; g_norm[i] = nrm; }
        else            { nrm = g_norm[i]; }
    }

    const float* src = (LAYER == 1) ? g_h1 : g_agg1;
    float*       dst = (LAYER == 1) ? g_agg1 : g_agg2;

    const float4* s = (const float4*)(src + (size_t)col * HID);
    float4 v0 = s[0], v1 = s[1], v2 = s[2], v3 = s[3];
    if (LAYER == 2) {
        const float4* b = (const float4*)b1;
        float4 b0 = b[0], bb = b[1], bc = b[2], bd = b[3];
        v0.x = fmaxf(v0.x + b0.x, 0.f); v0.y = fmaxf(v0.y + b0.y, 0.f);
        v0.z = fmaxf(v0.z + b0.z, 0.f); v0.w = fmaxf(v0.w + b0.w, 0.f);
        v1.x = fmaxf(v1.x + bb.x, 0.f); v1.y = fmaxf(v1.y + bb.y, 0.f);
        v1.z = fmaxf(v1.z + bb.z, 0.f); v1.w = fmaxf(v1.w + bb.w, 0.f);
        v2.x = fmaxf(v2.x + bc.x, 0.f); v2.y = fmaxf(v2.y + bc.y, 0.f);
        v2.z = fmaxf(v2.z + bc.z, 0.f); v2.w = fmaxf(v2.w + bc.w, 0.f);
        v3.x = fmaxf(v3.x + bd.x, 0.f); v3.y = fmaxf(v3.y + bd.y, 0.f);
        v3.z = fmaxf(v3.z + bd.z, 0.f); v3.w = fmaxf(v3.w + bd.w, 0.f);
    }
    v0.x *= nrm; v0.y *= nrm; v0.z *= nrm; v0.w *= nrm;
    v1.x *= nrm; v1.y *= nrm; v1.z *= nrm; v1.w *= nrm;
    v2.x *= nrm; v2.y *= nrm; v2.z *= nrm; v2.w *= nrm;
    v3.x *= nrm; v3.y *= nrm; v3.z *= nrm; v3.w *= nrm;

    float* d = dst + (size_t)row * HID;
    red_add_v4(d + 0,  v0);
    red_add_v4(d + 4,  v1);
    red_add_v4(d + 8,  v2);
    red_add_v4(d + 12, v3);
}

// ---------------------------------------------------------------- out = log_softmax(agg2 @ W2 + b2)
#define OUT_WARPS 8
__global__ void out_kernel(const float* __restrict__ W2, const float* __restrict__ b2,
                           float* __restrict__ out, int n) {
    __shared__ float W2s[HID * OUT_CH];
    for (int t = threadIdx.x; t < HID * OUT_CH / 4; t += blockDim.x)
        ((float4*)W2s)[t] = ((const float4*)W2)[t];
    __syncthreads();

    int warp = threadIdx.x >> 5, lane = threadIdx.x & 31;
    int node = blockIdx.x * OUT_WARPS + warp;
    if (node >= n) return;

    const float4* a4 = (const float4*)(g_agg2 + (size_t)node * HID);
    float4 a0 = a4[0], a1 = a4[1], a2 = a4[2], a3 = a4[3];
    float a[16];
    a[0]  = a0.x; a[1]  = a0.y; a[2]  = a0.z; a[3]  = a0.w;
    a[4]  = a1.x; a[5]  = a1.y; a[6]  = a1.z; a[7]  = a1.w;
    a[8]  = a2.x; a[9]  = a2.y; a[10] = a2.z; a[11] = a2.w;
    a[12] = a3.x; a[13] = a3.y; a[14] = a3.z; a[15] = a3.w;

    float acc0 = b2[lane];
    float acc1 = b2[lane + 32];
#pragma unroll
    for (int k = 0; k < HID; k++) {
        acc0 += a[k] * W2s[k * OUT_CH + lane];
        acc1 += a[k] * W2s[k * OUT_CH + lane + 32];
    }

    float m = fmaxf(acc0, acc1);
#pragma unroll
    for (int off = 16; off >= 1; off >>= 1)
        m = fmaxf(m, __shfl_xor_sync(0xffffffffu, m, off));
    float s = expf(acc0 - m) + expf(acc1 - m);
#pragma unroll
    for (int off = 16; off >= 1; off >>= 1)
        s += __shfl_xor_sync(0xffffffffu, s, off);
    float lse = m + logf(s);

    out[(size_t)node * OUT_CH + lane]      = acc0 - lse;
    out[(size_t)node * OUT_CH + lane + 32] = acc1 - lse;
}

// ---------------------------------------------------------------- launch
extern "C" void kernel_launch(void* const* d_in, const int* in_sizes, int n_in,
                              void* d_out, int out_size) {
    const float* x   = (const float*)d_in[0];
    const int*   ei1 = (const int*)  d_in[1];
    const float* ew1 = (const float*)d_in[2];
    const int*   ei2 = (const int*)  d_in[3];
    const float* ew2 = (const float*)d_in[4];
    const float* W1  = (const float*)d_in[5];
    const float* b1  = (const float*)d_in[6];
    const float* W2  = (const float*)d_in[7];
    const float* b2  = (const float*)d_in[8];
    float* out = (float*)d_out;

    int n  = in_sizes[0] / IN_CH;
    int E1 = in_sizes[2];
    int E2 = in_sizes[4];
    int Et = E1 + E2;

    const int G1_SMEM = G1_SMEM_FLOATS * (int)sizeof(float);
    cudaFuncSetAttribute(gemm1_kernel, cudaFuncAttributeMaxDynamicSharedMemorySize, G1_SMEM);

    zero_kernel<<<(n * HID + 255) / 256, 256>>>(n);
    deg_kernel<<<(Et + 255) / 256, 256>>>(ei1, ew1, E1, ei2, ew2, E2);
    dinv_kernel<<<(n + 255) / 256, 256>>>(n);
    gemm1_kernel<<<(n + G1_THREADS - 1) / G1_THREADS, G1_THREADS, G1_SMEM>>>(x, W1, n);
    scatter_kernel<1><<<(Et + 255) / 256, 256>>>(ei1, ew1, E1, ei2, ew2, E2, b1);
    scatter_kernel<2><<<(Et + 255) / 256, 256>>>(ei1, ew1, E1, ei2, ew2, E2, b1);
    out_kernel<<<(n + OUT_WARPS - 1) / OUT_WARPS, OUT_WARPS * 32>>>(W2, b2, out, n);
}

// round 4
// speedup vs baseline: 1.3671x; 1.3664x over previous
#include <cuda_runtime.h>
#include <cstdint>

#define IN_CH  512
#define HID    16
#define OUT_CH 64
#define MAX_NODES 100352
#define MAX_EDGES 3276800

// ---- scratch (device globals; no allocation allowed) ----
__device__ float g_deg [MAX_NODES];
__device__ float g_dinv[MAX_NODES];
__device__ float g_h1  [MAX_NODES * HID];
__device__ float g_agg1[MAX_NODES * HID];
__device__ float g_agg2[MAX_NODES * HID];
__device__ float g_norm[MAX_EDGES];

// vectorized f32 reduction (sm_90+): 1 request instead of 4 scalar atomics
__device__ __forceinline__ void red_add_v4(float* p, float4 v) {
    asm volatile("red.global.add.v4.f32 [%0], {%1,%2,%3,%4};"
                 :: "l"(p), "f"(v.x), "f"(v.y), "f"(v.z), "f"(v.w) : "memory");
}

// packed fp32x2 FMA (Blackwell FFMA2 — only reachable via PTX)
__device__ __forceinline__ void ffma2(unsigned long long& d, unsigned long long a,
                                      unsigned long long b) {
    asm("fma.rn.f32x2 %0, %1, %2, %0;" : "+l"(d) : "l"(a), "l"(b));
}

// ---------------------------------------------------------------- zero
__global__ void zero_kernel(int n) {
    int i = blockIdx.x * blockDim.x + threadIdx.x;
    int t4 = n * HID / 4;
    float4 z = make_float4(0.f, 0.f, 0.f, 0.f);
    if (i < t4) { ((float4*)g_agg1)[i] = z; ((float4*)g_agg2)[i] = z; }
    if (i < n) g_deg[i] = 0.f;
}

// ---------------------------------------------------------------- degree
__global__ void deg_kernel(const int* __restrict__ ei1, const float* __restrict__ w1, int E1,
                           const int* __restrict__ ei2, const float* __restrict__ w2, int E2) {
    int i = blockIdx.x * blockDim.x + threadIdx.x;
    if (i < E1) {
        atomicAdd(&g_deg[ei1[i]], w1[i]);
    } else {
        int j = i - E1;
        if (j < E2) atomicAdd(&g_deg[ei2[j]], w2[j]);
    }
}

__global__ void dinv_kernel(int n) {
    int i = blockIdx.x * blockDim.x + threadIdx.x;
    if (i >= n) return;
    float d = g_deg[i];
    g_dinv[i] = d > 0.f ? rsqrtf(fmaxf(d, 1e-12f)) : 0.f;
}

// ---------------------------------------------------------------- norm per edge
__global__ void norm_kernel(const int* __restrict__ ei1, const float* __restrict__ w1, int E1,
                            const int* __restrict__ ei2, const float* __restrict__ w2, int E2) {
    int i = blockIdx.x * blockDim.x + threadIdx.x;
    int row, col; float w;
    if (i < E1) {
        row = ei1[i]; col = ei1[E1 + i]; w = w1[i];
    } else {
        int j = i - E1;
        if (j >= E2) return;
        row = ei2[j]; col = ei2[E2 + j]; w = w2[j];
    }
    g_norm[i] = g_dinv[row] * w * g_dinv[col];
}

// ---------------------------------------------------------------- h1 = x @ W1
// lane-per-node, KCHUNK=32 keeps smem at 66KB -> 3 blocks/SM -> single wave.
// Inner loop uses packed fma.rn.f32x2: 8 FFMA2 + 1 LDS + 4 LDS.128 per k.
#define G1_WARPS   8
#define G1_THREADS (G1_WARPS * 32)
#define G1_KCHUNK  32
#define G1_XS_STRIDE 33
#define G1_SMEM_FLOATS (IN_CH * HID + G1_WARPS * 32 * G1_XS_STRIDE)

__global__ void __launch_bounds__(G1_THREADS, 3)
gemm1_kernel(const float* __restrict__ x, const float* __restrict__ W1, int n) {
    extern __shared__ float smem[];
    float* Ws = smem;  // [512][16] row-major, 32KB
    const int warp = threadIdx.x >> 5;
    const int lane = threadIdx.x & 31;
    float* xs = smem + IN_CH * HID + warp * (32 * G1_XS_STRIDE);

    for (int t = threadIdx.x; t < IN_CH * HID / 4; t += blockDim.x)
        ((float4*)Ws)[t] = ((const float4*)W1)[t];
    __syncthreads();

    const int nodebase = blockIdx.x * G1_THREADS + warp * 32;
    const int node = nodebase + lane;

    unsigned long long acc[8];
#pragma unroll
    for (int j = 0; j < 8; j++) acc[j] = 0ull;

    for (int kc = 0; kc < IN_CH; kc += G1_KCHUNK) {
        // stage 32 rows x 32 floats (coalesced float4 global loads)
#pragma unroll
        for (int t = 0; t < 8; t++) {
            int idx = t * 32 + lane;      // 0..255
            int r   = idx >> 3;           // row in tile
            int c   = idx & 7;            // float4 column
            int nd  = nodebase + r;
            float4 v = make_float4(0.f, 0.f, 0.f, 0.f);
            if (nd < n) v = ((const float4*)x)[(size_t)nd * (IN_CH / 4) + (kc >> 2) + c];
            float* p = xs + r * G1_XS_STRIDE + c * 4;   // conflict-free scalar stores
            p[0] = v.x; p[1] = v.y; p[2] = v.z; p[3] = v.w;
        }
        __syncwarp();
        const float* xrow = xs + lane * G1_XS_STRIDE;
#pragma unroll 8
        for (int k = 0; k < G1_KCHUNK; k++) {
            float xv = xrow[k];
            unsigned long long xx;
            asm("mov.b64 %0, {%1, %1};" : "=l"(xx) : "f"(xv));
            const ulonglong2* wr = (const ulonglong2*)(Ws + (kc + k) * HID);
            ulonglong2 w0 = wr[0], w1 = wr[1], w2 = wr[2], w3 = wr[3];
            ffma2(acc[0], w0.x, xx); ffma2(acc[1], w0.y, xx);
            ffma2(acc[2], w1.x, xx); ffma2(acc[3], w1.y, xx);
            ffma2(acc[4], w2.x, xx); ffma2(acc[5], w2.y, xx);
            ffma2(acc[6], w3.x, xx); ffma2(acc[7], w3.y, xx);
        }
        __syncwarp();
    }

    if (node < n) {
        float out[HID];
#pragma unroll
        for (int j = 0; j < 8; j++)
            asm("mov.b64 {%0, %1}, %2;" : "=f"(out[2*j]), "=f"(out[2*j+1]) : "l"(acc[j]));
        float4* o = (float4*)(g_h1 + (size_t)node * HID);
        o[0] = make_float4(out[0],  out[1],  out[2],  out[3]);
        o[1] = make_float4(out[4],  out[5],  out[6],  out[7]);
        o[2] = make_float4(out[8],  out[9],  out[10], out[11]);
        o[3] = make_float4(out[12], out[13], out[14], out[15]);
    }
}

// ---------------------------------------------------------------- scatter
// quad-per-edge: 4 consecutive lanes handle one edge, 16B (one float4) each.
// Gather warp-instruction touches ~8 distinct lines instead of ~32 -> 4x fewer
// L1tex wavefronts; same for the red.v4 line merge.
template <int LAYER>
__global__ void scatter_kernel(const int* __restrict__ ei1, int E1,
                               const int* __restrict__ ei2, int E2) {
    int t = blockIdx.x * blockDim.x + threadIdx.x;
    int e   = t >> 2;
    int sub = t & 3;
    int row, col;
    if (e < E1) {
        row = __ldg(ei1 + e); col = __ldg(ei1 + E1 + e);
    } else {
        int j = e - E1;
        if (j >= E2) return;
        row = __ldg(ei2 + j); col = __ldg(ei2 + E2 + j);
    }
    float nrm = __ldg(g_norm + e);

    const float* src = (LAYER == 1) ? g_h1 : g_agg1;
    float*       dst = (LAYER == 1) ? g_agg1 : g_agg2;

    float4 v = __ldg(((const float4*)(src + (size_t)col * HID)) + sub);
    v.x *= nrm; v.y *= nrm; v.z *= nrm; v.w *= nrm;
    red_add_v4(dst + (size_t)row * HID + sub * 4, v);
}

// ---------------------------------------------------------------- relu(agg1 + b1) in place
__global__ void relu_kernel(const float* __restrict__ b1, int n) {
    int i = blockIdx.x * blockDim.x + threadIdx.x;   // float4 index
    int t4 = n * HID / 4;
    if (i >= t4) return;
    float4 b = __ldg(((const float4*)b1) + (i & 3));
    float4 v = ((float4*)g_agg1)[i];
    v.x = fmaxf(v.x + b.x, 0.f);
    v.y = fmaxf(v.y + b.y, 0.f);
    v.z = fmaxf(v.z + b.z, 0.f);
    v.w = fmaxf(v.w + b.w, 0.f);
    ((float4*)g_agg1)[i] = v;
}

// ---------------------------------------------------------------- out = log_softmax(agg2 @ W2 + b2)
#define OUT_WARPS 8
__global__ void out_kernel(const float* __restrict__ W2, const float* __restrict__ b2,
                           float* __restrict__ out, int n) {
    __shared__ float W2s[HID * OUT_CH];
    for (int t = threadIdx.x; t < HID * OUT_CH / 4; t += blockDim.x)
        ((float4*)W2s)[t] = ((const float4*)W2)[t];
    __syncthreads();

    int warp = threadIdx.x >> 5, lane = threadIdx.x & 31;
    int node = blockIdx.x * OUT_WARPS + warp;
    if (node >= n) return;

    const float4* a4 = (const float4*)(g_agg2 + (size_t)node * HID);
    float4 a0 = a4[0], a1 = a4[1], a2 = a4[2], a3 = a4[3];
    float a[16];
    a[0]  = a0.x; a[1]  = a0.y; a[2]  = a0.z; a[3]  = a0.w;
    a[4]  = a1.x; a[5]  = a1.y; a[6]  = a1.z; a[7]  = a1.w;
    a[8]  = a2.x; a[9]  = a2.y; a[10] = a2.z; a[11] = a2.w;
    a[12] = a3.x; a[13] = a3.y; a[14] = a3.z; a[15] = a3.w;

    float acc0 = b2[lane];
    float acc1 = b2[lane + 32];
#pragma unroll
    for (int k = 0; k < HID; k++) {
        acc0 += a[k] * W2s[k * OUT_CH + lane];
        acc1 += a[k] * W2s[k * OUT_CH + lane + 32];
    }

    float m = fmaxf(acc0, acc1);
#pragma unroll
    for (int off = 16; off >= 1; off >>= 1)
        m = fmaxf(m, __shfl_xor_sync(0xffffffffu, m, off));
    float s = expf(acc0 - m) + expf(acc1 - m);
#pragma unroll
    for (int off = 16; off >= 1; off >>= 1)
        s += __shfl_xor_sync(0xffffffffu, s, off);
    float lse = m + logf(s);

    out[(size_t)node * OUT_CH + lane]      = acc0 - lse;
    out[(size_t)node * OUT_CH + lane + 32] = acc1 - lse;
}

// ---------------------------------------------------------------- launch
extern "C" void kernel_launch(void* const* d_in, const int* in_sizes, int n_in,
                              void* d_out, int out_size) {
    const float* x   = (const float*)d_in[0];
    const int*   ei1 = (const int*)  d_in[1];
    const float* ew1 = (const float*)d_in[2];
    const int*   ei2 = (const int*)  d_in[3];
    const float* ew2 = (const float*)d_in[4];
    const float* W1  = (const float*)d_in[5];
    const float* b1  = (const float*)d_in[6];
    const float* W2  = (const float*)d_in[7];
    const float* b2  = (const float*)d_in[8];
    float* out = (float*)d_out;

    int n  = in_sizes[0] / IN_CH;
    int E1 = in_sizes[2];
    int E2 = in_sizes[4];
    int Et = E1 + E2;

    const int G1_SMEM = G1_SMEM_FLOATS * (int)sizeof(float);
    cudaFuncSetAttribute(gemm1_kernel, cudaFuncAttributeMaxDynamicSharedMemorySize, G1_SMEM);

    zero_kernel<<<(n * HID / 4 + 255) / 256, 256>>>(n);
    deg_kernel<<<(Et + 255) / 256, 256>>>(ei1, ew1, E1, ei2, ew2, E2);
    dinv_kernel<<<(n + 255) / 256, 256>>>(n);
    norm_kernel<<<(Et + 255) / 256, 256>>>(ei1, ew1, E1, ei2, ew2, E2);
    gemm1_kernel<<<(n + G1_THREADS - 1) / G1_THREADS, G1_THREADS, G1_SMEM>>>(x, W1, n);
    scatter_kernel<1><<<(4 * Et + 255) / 256, 256>>>(ei1, E1, ei2, E2);
    relu_kernel<<<(n * HID / 4 + 255) / 256, 256>>>(b1, n);
    scatter_kernel<2><<<(4 * Et + 255) / 256, 256>>>(ei1, E1, ei2, E2);
    out_kernel<<<(n + OUT_WARPS - 1) / OUT_WARPS, OUT_WARPS * 32>>>(W2, b2, out, n);
}